// round 7
// baseline (speedup 1.0000x reference)
#include <cuda_runtime.h>
#include <cuda_bf16.h>
#include <cstdint>

#define EMB 1024
#define BB  4
#define NQS 1024
#define NKS 2048
#define NH  16
#define HD  64

// ---------------- scratch (no allocations allowed) ----------------
__device__ __nv_bfloat16 g_qh [(size_t)BB * NQS * EMB];
__device__ __nv_bfloat16 g_ql [(size_t)BB * NQS * EMB];
__device__ __nv_bfloat16 g_kh [(size_t)BB * NKS * EMB];
__device__ __nv_bfloat16 g_kl [(size_t)BB * NKS * EMB];
__device__ __nv_bfloat16 g_vh [(size_t)BB * NKS * EMB];
__device__ __nv_bfloat16 g_vl [(size_t)BB * NKS * EMB];
__device__ __nv_bfloat16 g_wh [4][(size_t)EMB * EMB];
__device__ __nv_bfloat16 g_wl [4][(size_t)EMB * EMB];
__device__ __nv_bfloat16 g_pqh[(size_t)BB * NQS * EMB];
__device__ __nv_bfloat16 g_pql[(size_t)BB * NQS * EMB];
__device__ __nv_bfloat16 g_pkh[(size_t)BB * NKS * EMB];
__device__ __nv_bfloat16 g_pkl[(size_t)BB * NKS * EMB];
__device__ __nv_bfloat16 g_pvh[(size_t)BB * NKS * EMB];
__device__ __nv_bfloat16 g_pvl[(size_t)BB * NKS * EMB];
__device__ __nv_bfloat16 g_aoh[(size_t)BB * NQS * EMB];
__device__ __nv_bfloat16 g_aol[(size_t)BB * NQS * EMB];
__device__ __align__(16) float g_logm[(size_t)BB * NKS];

// ================= helpers =================
__device__ __forceinline__ uint32_t smem_u32(const void* p) {
    uint32_t a;
    asm("{ .reg .u64 t; cvta.to.shared.u64 t, %1; cvt.u32.u64 %0, t; }" : "=r"(a) : "l"(p));
    return a;
}
__device__ __forceinline__ uint32_t ld_u32s(const __nv_bfloat16* p) {
    return *(const uint32_t*)p;
}
__device__ __forceinline__ uint32_t pack_bf(float lo, float hi) {
    uint32_t r;
    asm("cvt.rn.bf16x2.f32 %0, %1, %2;" : "=r"(r) : "f"(hi), "f"(lo));
    return r;
}
__device__ __forceinline__ float bfx2_lo(uint32_t v) { return __uint_as_float(v << 16); }
__device__ __forceinline__ float bfx2_hi(uint32_t v) { return __uint_as_float(v & 0xffff0000u); }

#define MMA16816(d, a, b0, b1)                                            \
    asm volatile("mma.sync.aligned.m16n8k16.row.col.f32.bf16.bf16.f32 "   \
                 "{%0,%1,%2,%3}, {%4,%5,%6,%7}, {%8,%9}, {%0,%1,%2,%3};"  \
                 : "+f"((d)[0]), "+f"((d)[1]), "+f"((d)[2]), "+f"((d)[3]) \
                 : "r"((a)[0]), "r"((a)[1]), "r"((a)[2]), "r"((a)[3]),    \
                   "r"(b0), "r"(b1))

#define LDSM_X4(r0, r1, r2, r3, addr)                                          \
    asm volatile("ldmatrix.sync.aligned.m8n8.x4.shared.b16 {%0,%1,%2,%3}, [%4];" \
                 : "=r"(r0), "=r"(r1), "=r"(r2), "=r"(r3) : "r"(addr))

#define LDSM_X4_T(r0, r1, r2, r3, addr)                                        \
    asm volatile("ldmatrix.sync.aligned.m8n8.x4.trans.shared.b16 "             \
                 "{%0,%1,%2,%3}, [%4];"                                        \
                 : "=r"(r0), "=r"(r1), "=r"(r2), "=r"(r3) : "r"(addr))

__device__ __forceinline__ void cp16(uint32_t dst, const void* src) {
    asm volatile("cp.async.cg.shared.global [%0], [%1], 16;" :: "r"(dst), "l"(src));
}
#define CP_COMMIT()  asm volatile("cp.async.commit_group;" ::: "memory")
#define CP_WAIT(n)   asm volatile("cp.async.wait_group %0;" :: "n"(n) : "memory")

// ============== split fp32 -> bf16 hi + bf16 lo ==================
__global__ __launch_bounds__(256)
void split_kernel(const float* __restrict__ x, __nv_bfloat16* __restrict__ hi,
                  __nv_bfloat16* __restrict__ lo, int n4)
{
    int i = blockIdx.x * blockDim.x + threadIdx.x;
    if (i >= n4) return;
    float4 v = ((const float4*)x)[i];
    uint32_t h0 = pack_bf(v.x, v.y), h1 = pack_bf(v.z, v.w);
    uint32_t l0 = pack_bf(v.x - bfx2_lo(h0), v.y - bfx2_hi(h0));
    uint32_t l1 = pack_bf(v.z - bfx2_lo(h1), v.w - bfx2_hi(h1));
    ((uint32_t*)hi)[2 * i] = h0; ((uint32_t*)hi)[2 * i + 1] = h1;
    ((uint32_t*)lo)[2 * i] = l0; ((uint32_t*)lo)[2 * i + 1] = l1;
}

__global__ __launch_bounds__(256)
void logm_kernel(const float* __restrict__ m, float* __restrict__ o, int n)
{
    int i = blockIdx.x * blockDim.x + threadIdx.x;
    if (i < n) o[i] = __logf(m[i]);
}

// ============== bf16x3 mma.sync GEMM, cp.async 2-stage ===========
#define LDT2 40
#define GT_ELEMS (128 * LDT2)
#define STAGE_ELEMS (4 * GT_ELEMS)
#define G_SMEM2 (2 * STAGE_ELEMS * 2)

__device__ __forceinline__ void stage_loads(uint32_t sbase,
                                            const __nv_bfloat16* Ah, const __nv_bfloat16* Al,
                                            const __nv_bfloat16* Wh, const __nv_bfloat16* Wl,
                                            size_t aoff, size_t woff, int K, int tid)
{
    const __nv_bfloat16* srcs[4] = {Ah + aoff, Al + aoff, Wh + woff, Wl + woff};
#pragma unroll
    for (int t = 0; t < 4; t++) {
        uint32_t tb = sbase + t * (GT_ELEMS * 2);
        const __nv_bfloat16* s = srcs[t];
#pragma unroll
        for (int j = 0; j < 2; j++) {
            int idx = tid + j * 256;
            int r = idx >> 2, c16 = idx & 3;
            cp16(tb + r * (LDT2 * 2) + c16 * 16,
                 s + (size_t)r * K + c16 * 8);
        }
    }
}

__global__ __launch_bounds__(256)
void gemm_bf16x3(const __nv_bfloat16* __restrict__ Ah, const __nv_bfloat16* __restrict__ Al,
                 const __nv_bfloat16* __restrict__ Wh, const __nv_bfloat16* __restrict__ Wl,
                 const float* __restrict__ bias, float* __restrict__ C,
                 __nv_bfloat16* __restrict__ Chi, __nv_bfloat16* __restrict__ Clo,
                 int M, int N, int K, int mode)
{
    extern __shared__ __nv_bfloat16 smb[];
    const uint32_t sb = smem_u32(smb);

    const int tid  = threadIdx.x;
    const int wid  = tid >> 5;
    const int lane = tid & 31;
    const int grp  = lane >> 2;
    const int tq   = lane & 3;
    const int wm   = wid >> 1;
    const int wn   = wid & 1;
    const int m0   = blockIdx.y * 128;
    const int n0   = blockIdx.x * 128;
    const int lrow = lane & 15;
    const int lcol = (lane >> 4) << 3;

    float d[2][8][4];
#pragma unroll
    for (int mt = 0; mt < 2; mt++)
#pragma unroll
        for (int nt = 0; nt < 8; nt++)
#pragma unroll
            for (int r = 0; r < 4; r++) d[mt][nt][r] = 0.f;

    const int nchunk = K >> 5;

    stage_loads(sb, Ah, Al, Wh, Wl, (size_t)m0 * K, (size_t)n0 * K, K, tid);
    CP_COMMIT();

    for (int c = 0; c < nchunk; c++) {
        if (c + 1 < nchunk) {
            stage_loads(sb + ((c + 1) & 1) * (STAGE_ELEMS * 2),
                        Ah, Al, Wh, Wl,
                        (size_t)m0 * K + (c + 1) * 32,
                        (size_t)n0 * K + (c + 1) * 32, K, tid);
            CP_COMMIT();
            CP_WAIT(1);
        } else {
            CP_WAIT(0);
        }
        __syncthreads();

        const uint32_t st = sb + (c & 1) * (STAGE_ELEMS * 2);
        const uint32_t sAh = st;
        const uint32_t sAl = st + 1 * (GT_ELEMS * 2);
        const uint32_t sWh = st + 2 * (GT_ELEMS * 2);
        const uint32_t sWl = st + 3 * (GT_ELEMS * 2);

#pragma unroll
        for (int kk = 0; kk < 32; kk += 16) {
            uint32_t ah[2][4], al[2][4];
#pragma unroll
            for (int mt = 0; mt < 2; mt++) {
                uint32_t ra = (uint32_t)((wm * 32 + mt * 16 + lrow) * (LDT2 * 2)
                                         + (kk + lcol) * 2);
                LDSM_X4(ah[mt][0], ah[mt][1], ah[mt][2], ah[mt][3], sAh + ra);
                LDSM_X4(al[mt][0], al[mt][1], al[mt][2], al[mt][3], sAl + ra);
            }
#pragma unroll
            for (int ntp = 0; ntp < 4; ntp++) {
                uint32_t rb = (uint32_t)((wn * 64 + ntp * 16 + lrow) * (LDT2 * 2)
                                         + (kk + lcol) * 2);
                uint32_t bh[4], bl[4];
                LDSM_X4(bh[0], bh[1], bh[2], bh[3], sWh + rb);
                LDSM_X4(bl[0], bl[1], bl[2], bl[3], sWl + rb);
#pragma unroll
                for (int sub = 0; sub < 2; sub++) {
                    int nt = ntp * 2 + sub;
#pragma unroll
                    for (int mt = 0; mt < 2; mt++) {
                        MMA16816(d[mt][nt], ah[mt], bh[sub], bh[2 + sub]);
                        MMA16816(d[mt][nt], al[mt], bh[sub], bh[2 + sub]);
                        MMA16816(d[mt][nt], ah[mt], bl[sub], bl[2 + sub]);
                    }
                }
            }
        }
        __syncthreads();
    }

#pragma unroll
    for (int mt = 0; mt < 2; mt++) {
        int r0 = m0 + wm * 32 + mt * 16 + grp;
#pragma unroll
        for (int nt = 0; nt < 8; nt++) {
            int cc = n0 + wn * 64 + nt * 8 + tq * 2;
            float b0 = bias[cc], b1 = bias[cc + 1];
            float v00 = d[mt][nt][0] + b0, v01 = d[mt][nt][1] + b1;
            float v10 = d[mt][nt][2] + b0, v11 = d[mt][nt][3] + b1;
            if (mode & 1) {
                *(float2*)(C + (size_t)r0 * N + cc)       = make_float2(v00, v01);
                *(float2*)(C + (size_t)(r0 + 8) * N + cc) = make_float2(v10, v11);
            }
            if (mode & 2) {
                uint32_t h0 = pack_bf(v00, v01), h1 = pack_bf(v10, v11);
                uint32_t l0 = pack_bf(v00 - bfx2_lo(h0), v01 - bfx2_hi(h0));
                uint32_t l1 = pack_bf(v10 - bfx2_lo(h1), v11 - bfx2_hi(h1));
                *(uint32_t*)(Chi + (size_t)r0 * N + cc)       = h0;
                *(uint32_t*)(Chi + (size_t)(r0 + 8) * N + cc) = h1;
                *(uint32_t*)(Clo + (size_t)r0 * N + cc)       = l0;
                *(uint32_t*)(Clo + (size_t)(r0 + 8) * N + cc) = l1;
            }
        }
    }
}

// =================================================================
// Tensor-core attention: cp.async 2-stage K/V pipeline + ldmatrix.
// smem: 2 stages x (Kh,Kl,Vh,Vl 64x72) + Qh,Ql tiles = 92160 B.
// =================================================================
#define ALDT 72
#define KV_TILE (64 * ALDT)
#define KV_STAGE (4 * KV_TILE)
#define AQ_OFF (2 * KV_STAGE)
#define ATTN_SMEM ((2 * KV_STAGE + 2 * KV_TILE) * 2)

__device__ __forceinline__ void stage_kv(uint32_t sbase,
                                         const __nv_bfloat16* Kh, const __nv_bfloat16* Kl,
                                         const __nv_bfloat16* Vh, const __nv_bfloat16* Vl,
                                         size_t kbase, int k0, int tid)
{
    const __nv_bfloat16* srcs[4] = {Kh, Kl, Vh, Vl};
#pragma unroll
    for (int t = 0; t < 4; t++) {
        uint32_t tb = sbase + t * (KV_TILE * 2);
        const __nv_bfloat16* s = srcs[t];
#pragma unroll
        for (int j = 0; j < 4; j++) {
            int idx = tid + j * 128;
            int r = idx >> 3, c16 = idx & 7;
            cp16(tb + r * (ALDT * 2) + c16 * 16,
                 s + kbase + (size_t)(k0 + r) * EMB + c16 * 8);
        }
    }
}

__global__ __launch_bounds__(128)
void attn_mma(const __nv_bfloat16* __restrict__ Qh, const __nv_bfloat16* __restrict__ Ql,
              const __nv_bfloat16* __restrict__ Kh, const __nv_bfloat16* __restrict__ Kl,
              const __nv_bfloat16* __restrict__ Vh, const __nv_bfloat16* __restrict__ Vl,
              const float* __restrict__ logm,
              __nv_bfloat16* __restrict__ Ohi, __nv_bfloat16* __restrict__ Olo)
{
    extern __shared__ __nv_bfloat16 smb[];
    const uint32_t sb = smem_u32(smb);
    __nv_bfloat16* sQh = smb + AQ_OFF;
    __nv_bfloat16* sQl = smb + AQ_OFF + KV_TILE;

    const int tid  = threadIdx.x;
    const int wid  = tid >> 5;
    const int lane = tid & 31;
    const int grp  = lane >> 2;
    const int tq   = lane & 3;
    const int lrow = lane & 15;
    const int lcol = (lane >> 4) << 3;
    const int qb   = blockIdx.x;
    const int h    = blockIdx.y;
    const int b    = blockIdx.z;

    const size_t qoff  = ((size_t)(b * NQS + qb * 64)) * EMB + h * HD;
    const size_t kbase = ((size_t)b * NKS) * EMB + h * HD;
    const float* Lg = logm + b * NKS;

    // stage Q tile (64x64) once
#pragma unroll
    for (int i = 0; i < 4; i++) {
        int idx = tid + i * 128;
        int r = idx >> 3, c8 = idx & 7;
        *(float4*)(sQh + r * ALDT + c8 * 8) = *(const float4*)(Qh + qoff + (size_t)r * EMB + c8 * 8);
        *(float4*)(sQl + r * ALDT + c8 * 8) = *(const float4*)(Ql + qoff + (size_t)r * EMB + c8 * 8);
    }

    // prologue: stage chunk 0
    stage_kv(sb, Kh, Kl, Vh, Vl, kbase, 0, tid);
    CP_COMMIT();
    __syncthreads();

    // Q fragments in registers for whole kernel
    uint32_t aqh[4][4], aql[4][4];
#pragma unroll
    for (int ks = 0; ks < 4; ks++) {
        int r = wid * 16 + grp;
        int c = ks * 16 + tq * 2;
        aqh[ks][0] = ld_u32s(sQh + (r    ) * ALDT + c    );
        aqh[ks][1] = ld_u32s(sQh + (r + 8) * ALDT + c    );
        aqh[ks][2] = ld_u32s(sQh + (r    ) * ALDT + c + 8);
        aqh[ks][3] = ld_u32s(sQh + (r + 8) * ALDT + c + 8);
        aql[ks][0] = ld_u32s(sQl + (r    ) * ALDT + c    );
        aql[ks][1] = ld_u32s(sQl + (r + 8) * ALDT + c    );
        aql[ks][2] = ld_u32s(sQl + (r    ) * ALDT + c + 8);
        aql[ks][3] = ld_u32s(sQl + (r + 8) * ALDT + c + 8);
    }

    float dO[8][4];
#pragma unroll
    for (int nt = 0; nt < 8; nt++)
#pragma unroll
        for (int r = 0; r < 4; r++) dO[nt][r] = 0.f;
    float mrun0 = -3.4e38f, mrun1 = -3.4e38f, lrun0 = 0.f, lrun1 = 0.f;

    const int nchunk = NKS / 64;
    for (int c = 0; c < nchunk; c++) {
        if (c + 1 < nchunk) {
            stage_kv(sb + ((c + 1) & 1) * (KV_STAGE * 2),
                     Kh, Kl, Vh, Vl, kbase, (c + 1) * 64, tid);
            CP_COMMIT();
            CP_WAIT(1);
        } else {
            CP_WAIT(0);
        }
        __syncthreads();

        const uint32_t st  = sb + (c & 1) * (KV_STAGE * 2);
        const uint32_t sKh = st;
        const uint32_t sKl = st + 1 * (KV_TILE * 2);
        const uint32_t sVh = st + 2 * (KV_TILE * 2);
        const uint32_t sVl = st + 3 * (KV_TILE * 2);
        const int k0 = c * 64;

        // prefetch log-multiplicities for this chunk
        float lmv[8][2];
#pragma unroll
        for (int nt = 0; nt < 8; nt++) {
            lmv[nt][0] = Lg[k0 + nt * 8 + tq * 2];
            lmv[nt][1] = Lg[k0 + nt * 8 + tq * 2 + 1];
        }

        // S = Q @ K^T (bf16x3) via ldmatrix B fragments
        float dS[8][4];
#pragma unroll
        for (int nt = 0; nt < 8; nt++)
#pragma unroll
            for (int r = 0; r < 4; r++) dS[nt][r] = 0.f;

#pragma unroll
        for (int ks = 0; ks < 4; ks++) {
#pragma unroll
            for (int ntp = 0; ntp < 4; ntp++) {
                uint32_t rb = (uint32_t)((ntp * 16 + lrow) * (ALDT * 2)
                                         + (ks * 16 + lcol) * 2);
                uint32_t bh[4], bl[4];
                LDSM_X4(bh[0], bh[1], bh[2], bh[3], sKh + rb);
                LDSM_X4(bl[0], bl[1], bl[2], bl[3], sKl + rb);
#pragma unroll
                for (int sub = 0; sub < 2; sub++) {
                    int nt = ntp * 2 + sub;
                    MMA16816(dS[nt], aqh[ks], bh[sub], bh[2 + sub]);
                    MMA16816(dS[nt], aql[ks], bh[sub], bh[2 + sub]);
                    MMA16816(dS[nt], aqh[ks], bl[sub], bl[2 + sub]);
                }
            }
        }

        // logits + online softmax on fragments
        float mx0 = -3.4e38f, mx1 = -3.4e38f;
#pragma unroll
        for (int nt = 0; nt < 8; nt++) {
            dS[nt][0] = dS[nt][0] * 0.125f + lmv[nt][0];
            dS[nt][1] = dS[nt][1] * 0.125f + lmv[nt][1];
            dS[nt][2] = dS[nt][2] * 0.125f + lmv[nt][0];
            dS[nt][3] = dS[nt][3] * 0.125f + lmv[nt][1];
            mx0 = fmaxf(mx0, fmaxf(dS[nt][0], dS[nt][1]));
            mx1 = fmaxf(mx1, fmaxf(dS[nt][2], dS[nt][3]));
        }
        mx0 = fmaxf(mx0, __shfl_xor_sync(0xffffffffu, mx0, 1));
        mx0 = fmaxf(mx0, __shfl_xor_sync(0xffffffffu, mx0, 2));
        mx1 = fmaxf(mx1, __shfl_xor_sync(0xffffffffu, mx1, 1));
        mx1 = fmaxf(mx1, __shfl_xor_sync(0xffffffffu, mx1, 2));
        float mnew0 = fmaxf(mrun0, mx0), mnew1 = fmaxf(mrun1, mx1);
        float corr0 = __expf(mrun0 - mnew0), corr1 = __expf(mrun1 - mnew1);
        float rs0 = 0.f, rs1 = 0.f;
#pragma unroll
        for (int nt = 0; nt < 8; nt++) {
            dS[nt][0] = __expf(dS[nt][0] - mnew0); rs0 += dS[nt][0];
            dS[nt][1] = __expf(dS[nt][1] - mnew0); rs0 += dS[nt][1];
            dS[nt][2] = __expf(dS[nt][2] - mnew1); rs1 += dS[nt][2];
            dS[nt][3] = __expf(dS[nt][3] - mnew1); rs1 += dS[nt][3];
        }
        rs0 += __shfl_xor_sync(0xffffffffu, rs0, 1);
        rs0 += __shfl_xor_sync(0xffffffffu, rs0, 2);
        rs1 += __shfl_xor_sync(0xffffffffu, rs1, 1);
        rs1 += __shfl_xor_sync(0xffffffffu, rs1, 2);
        lrun0 = lrun0 * corr0 + rs0; mrun0 = mnew0;
        lrun1 = lrun1 * corr1 + rs1; mrun1 = mnew1;
#pragma unroll
        for (int nt = 0; nt < 8; nt++) {
            dO[nt][0] *= corr0; dO[nt][1] *= corr0;
            dO[nt][2] *= corr1; dO[nt][3] *= corr1;
        }

        // O += P @ V
#pragma unroll
        for (int kb = 0; kb < 4; kb++) {
            uint32_t ph[4], pl[4];
            ph[0] = pack_bf(dS[2 * kb][0],     dS[2 * kb][1]);
            ph[1] = pack_bf(dS[2 * kb][2],     dS[2 * kb][3]);
            ph[2] = pack_bf(dS[2 * kb + 1][0], dS[2 * kb + 1][1]);
            ph[3] = pack_bf(dS[2 * kb + 1][2], dS[2 * kb + 1][3]);
            pl[0] = pack_bf(dS[2 * kb][0] - bfx2_lo(ph[0]),     dS[2 * kb][1] - bfx2_hi(ph[0]));
            pl[1] = pack_bf(dS[2 * kb][2] - bfx2_lo(ph[1]),     dS[2 * kb][3] - bfx2_hi(ph[1]));
            pl[2] = pack_bf(dS[2 * kb + 1][0] - bfx2_lo(ph[2]), dS[2 * kb + 1][1] - bfx2_hi(ph[2]));
            pl[3] = pack_bf(dS[2 * kb + 1][2] - bfx2_lo(ph[3]), dS[2 * kb + 1][3] - bfx2_hi(ph[3]));

#pragma unroll
            for (int np = 0; np < 4; np++) {
                uint32_t off = (uint32_t)((kb * 16 + lrow) * ALDT
                                          + np * 16 + lcol) * 2;
                uint32_t vh[4], vl[4];
                LDSM_X4_T(vh[0], vh[1], vh[2], vh[3], sVh + off);
                LDSM_X4_T(vl[0], vl[1], vl[2], vl[3], sVl + off);
                MMA16816(dO[2 * np],     ph, vh[0], vh[1]);
                MMA16816(dO[2 * np],     pl, vh[0], vh[1]);
                MMA16816(dO[2 * np],     ph, vl[0], vl[1]);
                MMA16816(dO[2 * np + 1], ph, vh[2], vh[3]);
                MMA16816(dO[2 * np + 1], pl, vh[2], vh[3]);
                MMA16816(dO[2 * np + 1], ph, vl[2], vl[3]);
            }
        }
        __syncthreads();
    }

    float inv0 = 1.f / lrun0, inv1 = 1.f / lrun1;
    int gr0 = qb * 64 + wid * 16 + grp;
#pragma unroll
    for (int nt = 0; nt < 8; nt++) {
        int col = h * HD + nt * 8 + tq * 2;
        float o00 = dO[nt][0] * inv0, o01 = dO[nt][1] * inv0;
        float o10 = dO[nt][2] * inv1, o11 = dO[nt][3] * inv1;
        uint32_t h0 = pack_bf(o00, o01), h1 = pack_bf(o10, o11);
        uint32_t l0 = pack_bf(o00 - bfx2_lo(h0), o01 - bfx2_hi(h0));
        uint32_t l1 = pack_bf(o10 - bfx2_lo(h1), o11 - bfx2_hi(h1));
        size_t p0 = ((size_t)(b * NQS + gr0)) * EMB + col;
        size_t p1 = ((size_t)(b * NQS + gr0 + 8)) * EMB + col;
        *(uint32_t*)(Ohi + p0) = h0; *(uint32_t*)(Ohi + p1) = h1;
        *(uint32_t*)(Olo + p0) = l0; *(uint32_t*)(Olo + p1) = l1;
    }
}

// =================================================================
extern "C" void kernel_launch(void* const* d_in, const int* in_sizes, int n_in,
                              void* d_out, int out_size)
{
    const float* query = (const float*)d_in[0];
    const float* key_  = (const float*)d_in[1];
    const float* value = (const float*)d_in[2];
    const float* mult  = (const float*)d_in[3];
    const float* wq_w  = (const float*)d_in[4];
    const float* wq_b  = (const float*)d_in[5];
    const float* wk_w  = (const float*)d_in[6];
    const float* wk_b  = (const float*)d_in[7];
    const float* wv_w  = (const float*)d_in[8];
    const float* wv_b  = (const float*)d_in[9];
    const float* wo_w  = (const float*)d_in[10];
    const float* wo_b  = (const float*)d_in[11];
    float* out = (float*)d_out;

    __nv_bfloat16 *qh, *ql, *kh, *kl, *vh, *vl, *wh, *wl;
    __nv_bfloat16 *pqh, *pql, *pkh, *pkl, *pvh, *pvl, *aoh, *aol;
    float* logm;
    cudaGetSymbolAddress((void**)&qh,  g_qh);
    cudaGetSymbolAddress((void**)&ql,  g_ql);
    cudaGetSymbolAddress((void**)&kh,  g_kh);
    cudaGetSymbolAddress((void**)&kl,  g_kl);
    cudaGetSymbolAddress((void**)&vh,  g_vh);
    cudaGetSymbolAddress((void**)&vl,  g_vl);
    cudaGetSymbolAddress((void**)&wh,  g_wh);
    cudaGetSymbolAddress((void**)&wl,  g_wl);
    cudaGetSymbolAddress((void**)&pqh, g_pqh);
    cudaGetSymbolAddress((void**)&pql, g_pql);
    cudaGetSymbolAddress((void**)&pkh, g_pkh);
    cudaGetSymbolAddress((void**)&pkl, g_pkl);
    cudaGetSymbolAddress((void**)&pvh, g_pvh);
    cudaGetSymbolAddress((void**)&pvl, g_pvl);
    cudaGetSymbolAddress((void**)&aoh, g_aoh);
    cudaGetSymbolAddress((void**)&aol, g_aol);
    cudaGetSymbolAddress((void**)&logm, g_logm);

    cudaFuncSetAttribute(gemm_bf16x3,
                         cudaFuncAttributeMaxDynamicSharedMemorySize, G_SMEM2);
    cudaFuncSetAttribute(attn_mma,
                         cudaFuncAttributeMaxDynamicSharedMemorySize, ATTN_SMEM);

    const size_t WSZ = (size_t)EMB * EMB;
    const int nq4 = BB * NQS * EMB / 4, nk4 = BB * NKS * EMB / 4, nw4 = (int)(WSZ / 4);

    dim3 gq(EMB / 128, (BB * NQS) / 128);   // (8, 32)
    dim3 gk(EMB / 128, (BB * NKS) / 128);   // (8, 64)

    // launches 1-5: splits needed by gemm_q (so launch #6 = gemm_q gets profiled)
    split_kernel<<<(nq4 + 255) / 256, 256>>>(query, qh, ql, nq4);
    split_kernel<<<(nw4 + 255) / 256, 256>>>(wq_w, wh + 0 * WSZ, wl + 0 * WSZ, nw4);
    split_kernel<<<(nk4 + 255) / 256, 256>>>(key_,  kh, kl, nk4);
    split_kernel<<<(nw4 + 255) / 256, 256>>>(wk_w, wh + 1 * WSZ, wl + 1 * WSZ, nw4);
    split_kernel<<<(nk4 + 255) / 256, 256>>>(value, vh, vl, nk4);

    // launch 6: Q projection (ncu -s 5 -c 1 profiles this one)
    gemm_bf16x3<<<gq, 256, G_SMEM2>>>(qh, ql, wh + 0 * WSZ, wl + 0 * WSZ, wq_b,
                                      out, pqh, pql, BB * NQS, EMB, EMB, 2);

    split_kernel<<<(nw4 + 255) / 256, 256>>>(wv_w, wh + 2 * WSZ, wl + 2 * WSZ, nw4);
    split_kernel<<<(nw4 + 255) / 256, 256>>>(wo_w, wh + 3 * WSZ, wl + 3 * WSZ, nw4);
    logm_kernel<<<(BB * NKS + 255) / 256, 256>>>(mult, logm, BB * NKS);

    gemm_bf16x3<<<gk, 256, G_SMEM2>>>(kh, kl, wh + 1 * WSZ, wl + 1 * WSZ, wk_b,
                                      out, pkh, pkl, BB * NKS, EMB, EMB, 2);
    gemm_bf16x3<<<gk, 256, G_SMEM2>>>(vh, vl, wh + 2 * WSZ, wl + 2 * WSZ, wv_b,
                                      out, pvh, pvl, BB * NKS, EMB, EMB, 2);

    dim3 ga(NQS / 64, NH, BB);              // (16, 16, 4)
    attn_mma<<<ga, 128, ATTN_SMEM>>>(pqh, pql, pkh, pkl, pvh, pvl, logm, aoh, aol);

    gemm_bf16x3<<<gq, 256, G_SMEM2>>>(aoh, aol, wh + 3 * WSZ, wl + 3 * WSZ, wo_b,
                                      out, aoh, aol, BB * NQS, EMB, EMB, 1);
}